// round 4
// baseline (speedup 1.0000x reference)
#include <cuda_runtime.h>
#include <cstdint>

#define CIN 16
#define COUT 32
#define K2 9
#define MAXN 2000000

// Intermediate h1 = relu(conv1(x)) : [N, 32] fp32 (256 MB scratch).
__device__ float g_h1[(size_t)MAXN * COUT];
// Always-valid zero row for masked / out-of-range gathers.
__device__ __align__(16) float g_zero[COUT] = {};

typedef unsigned long long ull;

__device__ __forceinline__ ull pack2(float a, float b) {
    ull r; asm("mov.b64 %0, {%1, %2};" : "=l"(r) : "f"(a), "f"(b)); return r;
}
__device__ __forceinline__ float2 unpack2(ull v) {
    float2 f; asm("mov.b64 {%0, %1}, %2;" : "=f"(f.x), "=f"(f.y) : "l"(v)); return f;
}
__device__ __forceinline__ ull fma2(ull a, ull b, ull c) {
    ull d; asm("fma.rn.f32x2 %0, %1, %2, %3;" : "=l"(d) : "l"(a), "l"(b), "l"(c)); return d;
}
__device__ __forceinline__ void cp16(uint32_t dst, const float* src) {
    asm volatile("cp.async.cg.shared.global [%0], [%1], 16;" :: "r"(dst), "l"(src));
}
__device__ __forceinline__ void cp_commit() {
    asm volatile("cp.async.commit_group;" ::: "memory");
}
template <int N>
__device__ __forceinline__ void cp_wait() {
    asm volatile("cp.async.wait_group %0;" :: "n"(N) : "memory");
}

// Buffer row strides (floats): 16B-aligned, bank-conflict-free for ty-step access.
#define S1 20   // conv1: 16 data + 4 pad  (ty bank step 20)
#define S2 36   // conv2: 32 data + 4 pad  (ty bank step 4)

// Tiling: 256 threads, tile 256 voxels x 32 couts.
// tx = tid&7 -> couts [4*tx,4*tx+4); ty = tid>>3 (0..31) -> rows {ty + 32*vi}.

// =====================================================================
// conv1: h1 = relu( sum_k mask*x[idx] @ W1[k] + b1 )
// =====================================================================
__global__ __launch_bounds__(256)
void conv1_kernel(const float* __restrict__ x,
                  const float* __restrict__ W1,
                  const float* __restrict__ b1,
                  const int* __restrict__ nbr_idx,
                  const unsigned int* __restrict__ nbr_mask,
                  int n) {
    extern __shared__ char smem[];
    float* buf = (float*)smem;                               // 2 x 256 x S1
    ull* Ws = (ull*)(smem + 2 * 256 * S1 * sizeof(float));   // 9*16*16 ull
    ull* bs = Ws + K2 * CIN * (COUT / 2);

    const int t  = threadIdx.x;
    const int tx = t & 7;
    const int ty = t >> 3;
    const int v0 = blockIdx.x * 256;
    const uint32_t sbase = (uint32_t)__cvta_generic_to_shared(buf);

    // stage tap k into buffer b: thread t gathers row t (4 x 16B chunks)
    auto stage = [&](int k, int b) {
        const float* src = g_zero;
        int v = v0 + t;
        if (v < n) {
            size_t off = (size_t)k * n + v;
            if (nbr_mask[off]) src = x + (size_t)nbr_idx[off] * CIN;
        }
        uint32_t d = sbase + (uint32_t)(b * 256 * S1 + t * S1) * 4u;
#pragma unroll
        for (int q = 0; q < 4; q++) cp16(d + q * 16, src + q * 4);
    };

    // get tap 0 gathers in flight ASAP
    stage(0, 0); cp_commit();

    // weights -> smem as f32x2 pairs
    for (int i = t; i < K2 * CIN * (COUT / 2); i += 256) {
        int row = i >> 4, p = i & 15;
        Ws[i] = pack2(W1[row * COUT + 2 * p], W1[row * COUT + 2 * p + 1]);
    }
    if (t < COUT / 2) bs[t] = pack2(b1[2 * t], b1[2 * t + 1]);
    __syncthreads();

    ull acc[8][2];
    {
        ull bw0 = bs[tx * 2], bw1 = bs[tx * 2 + 1];
#pragma unroll
        for (int vi = 0; vi < 8; vi++) { acc[vi][0] = bw0; acc[vi][1] = bw1; }
    }

    for (int k = 0; k < K2; k++) {
        if (k < K2 - 1) { stage(k + 1, (k + 1) & 1); cp_commit(); cp_wait<1>(); }
        else            { cp_wait<0>(); }
        __syncthreads();
        const ull* wk = Ws + k * (CIN * (COUT / 2));
        const float* bk = buf + (k & 1) * 256 * S1;
#pragma unroll
        for (int c = 0; c < CIN; c++) {
            ull w0 = wk[c * (COUT / 2) + tx * 2];
            ull w1 = wk[c * (COUT / 2) + tx * 2 + 1];
#pragma unroll
            for (int vi = 0; vi < 8; vi++) {
                float h = bk[(ty + 32 * vi) * S1 + c];
                ull hh = pack2(h, h);
                acc[vi][0] = fma2(hh, w0, acc[vi][0]);
                acc[vi][1] = fma2(hh, w1, acc[vi][1]);
            }
        }
        __syncthreads();
    }

#pragma unroll
    for (int vi = 0; vi < 8; vi++) {
        int v = v0 + ty + 32 * vi;
        if (v < n) {
            float2 a = unpack2(acc[vi][0]), b = unpack2(acc[vi][1]);
            *((float4*)(g_h1 + (size_t)v * COUT + tx * 4)) =
                make_float4(fmaxf(a.x, 0.f), fmaxf(a.y, 0.f),
                            fmaxf(b.x, 0.f), fmaxf(b.y, 0.f));
        }
    }
}

// =====================================================================
// conv2 + residual: out = relu( sum_k mask*h1[idx] @ W2[k] + b2 + x @ Wp + bp )
// =====================================================================
__global__ __launch_bounds__(256)
void conv2_kernel(const float* __restrict__ x,
                  const float* __restrict__ W2,
                  const float* __restrict__ b2,
                  const float* __restrict__ Wp,
                  const float* __restrict__ bp,
                  const int* __restrict__ nbr_idx,
                  const unsigned int* __restrict__ nbr_mask,
                  float* __restrict__ out,
                  int n) {
    extern __shared__ char smem[];
    float* buf = (float*)smem;                                // 2 x 256 x S2
    ull* Ws2 = (ull*)(smem + 2 * 256 * S2 * sizeof(float));   // 9*32*16 ull
    ull* Wps = Ws2 + K2 * COUT * (COUT / 2);                  // 16*16 ull
    ull* bs  = Wps + CIN * (COUT / 2);

    const int t  = threadIdx.x;
    const int tx = t & 7;
    const int ty = t >> 3;
    const int v0 = blockIdx.x * 256;
    const uint32_t sbase = (uint32_t)__cvta_generic_to_shared(buf);

    // stage conv tap k into buffer b (8 x 16B chunks of the gathered h1 row)
    auto stage = [&](int k, int b) {
        const float* src = g_zero;
        int v = v0 + t;
        if (v < n) {
            size_t off = (size_t)k * n + v;
            if (nbr_mask[off]) src = g_h1 + (size_t)nbr_idx[off] * COUT;
        }
        uint32_t d = sbase + (uint32_t)(b * 256 * S2 + t * S2) * 4u;
#pragma unroll
        for (int q = 0; q < 8; q++) cp16(d + q * 16, src + q * 4);
    };
    // stage own x row (residual projection) into buffer 0, cols 0..15
    auto stage_proj = [&]() {
        int v = v0 + t;
        const float* src = (v < n) ? (x + (size_t)v * CIN) : g_zero;
        uint32_t d = sbase + (uint32_t)(t * S2) * 4u;
#pragma unroll
        for (int q = 0; q < 4; q++) cp16(d + q * 16, src + q * 4);
    };

    stage_proj();  cp_commit();   // group: proj  -> buf0
    stage(0, 1);   cp_commit();   // group: tap0  -> buf1

    // weights -> smem pairs
    for (int i = t; i < K2 * COUT * (COUT / 2); i += 256) {
        int row = i >> 4, p = i & 15;
        Ws2[i] = pack2(W2[row * COUT + 2 * p], W2[row * COUT + 2 * p + 1]);
    }
    for (int i = t; i < CIN * (COUT / 2); i += 256) {
        int row = i >> 4, p = i & 15;
        Wps[i] = pack2(Wp[row * COUT + 2 * p], Wp[row * COUT + 2 * p + 1]);
    }
    if (t < COUT / 2)
        bs[t] = pack2(b2[2 * t] + bp[2 * t], b2[2 * t + 1] + bp[2 * t + 1]);
    __syncthreads();

    ull acc[8][2];
    {
        ull bw0 = bs[tx * 2], bw1 = bs[tx * 2 + 1];
#pragma unroll
        for (int vi = 0; vi < 8; vi++) { acc[vi][0] = bw0; acc[vi][1] = bw1; }
    }

    // ---- residual projection from buf0 (16 c-steps) ----
    cp_wait<1>();
    __syncthreads();
#pragma unroll
    for (int c = 0; c < CIN; c++) {
        ull w0 = Wps[c * (COUT / 2) + tx * 2];
        ull w1 = Wps[c * (COUT / 2) + tx * 2 + 1];
#pragma unroll
        for (int vi = 0; vi < 8; vi++) {
            float h = buf[(ty + 32 * vi) * S2 + c];
            ull hh = pack2(h, h);
            acc[vi][0] = fma2(hh, w0, acc[vi][0]);
            acc[vi][1] = fma2(hh, w1, acc[vi][1]);
        }
    }
    __syncthreads();

    // ---- 9 conv taps, double buffered: tap k lives in buf (k+1)&1 ----
    for (int k = 0; k < K2; k++) {
        if (k < K2 - 1) { stage(k + 1, k & 1); cp_commit(); cp_wait<1>(); }
        else            { cp_wait<0>(); }
        __syncthreads();
        const ull* wk = Ws2 + k * (COUT * (COUT / 2));
        const float* bk = buf + ((k + 1) & 1) * 256 * S2;
#pragma unroll
        for (int c = 0; c < COUT; c++) {
            ull w0 = wk[c * (COUT / 2) + tx * 2];
            ull w1 = wk[c * (COUT / 2) + tx * 2 + 1];
#pragma unroll
            for (int vi = 0; vi < 8; vi++) {
                float h = bk[(ty + 32 * vi) * S2 + c];
                ull hh = pack2(h, h);
                acc[vi][0] = fma2(hh, w0, acc[vi][0]);
                acc[vi][1] = fma2(hh, w1, acc[vi][1]);
            }
        }
        __syncthreads();
    }

#pragma unroll
    for (int vi = 0; vi < 8; vi++) {
        int v = v0 + ty + 32 * vi;
        if (v < n) {
            float2 a = unpack2(acc[vi][0]), b = unpack2(acc[vi][1]);
            *((float4*)(out + (size_t)v * COUT + tx * 4)) =
                make_float4(fmaxf(a.x, 0.f), fmaxf(a.y, 0.f),
                            fmaxf(b.x, 0.f), fmaxf(b.y, 0.f));
        }
    }
}

// =====================================================================
// Launch.  Input order: x, W1, b1, W2, b2, Wp, bp, nbr_idx, nbr_mask
// =====================================================================
extern "C" void kernel_launch(void* const* d_in, const int* in_sizes, int n_in,
                              void* d_out, int out_size) {
    const float* x  = (const float*)d_in[0];
    const float* W1 = (const float*)d_in[1];
    const float* b1 = (const float*)d_in[2];
    const float* W2 = (const float*)d_in[3];
    const float* b2 = (const float*)d_in[4];
    const float* Wp = (const float*)d_in[5];
    const float* bp = (const float*)d_in[6];
    const int* nbr_idx = (const int*)d_in[7];
    const unsigned int* nbr_mask = (const unsigned int*)d_in[8];
    float* out = (float*)d_out;

    int n = in_sizes[0] / CIN;
    if (n > MAXN) n = MAXN;

    const int smem1 = 2 * 256 * S1 * 4 + (K2 * CIN * (COUT / 2) + COUT / 2) * 8;
    const int smem2 = 2 * 256 * S2 * 4 +
                      (K2 * COUT * (COUT / 2) + CIN * (COUT / 2) + COUT / 2) * 8;

    cudaFuncSetAttribute(conv1_kernel, cudaFuncAttributeMaxDynamicSharedMemorySize, smem1);
    cudaFuncSetAttribute(conv2_kernel, cudaFuncAttributeMaxDynamicSharedMemorySize, smem2);

    int blocks = (n + 255) / 256;
    conv1_kernel<<<blocks, 256, smem1>>>(x, W1, b1, nbr_idx, nbr_mask, n);
    conv2_kernel<<<blocks, 256, smem2>>>(x, W2, b2, Wp, bp, nbr_idx, nbr_mask, out, n);
}

// round 5
// speedup vs baseline: 2.9301x; 2.9301x over previous
#include <cuda_runtime.h>
#include <cstdint>

#define CIN 16
#define COUT 32
#define K2 9
#define MAXN 2000000
#define ST 34   // transposed tile row stride in floats (conflict-free LDS.64)

// Intermediate h1 = relu(conv1(x)) : [N, 32] fp32 (256 MB scratch).
__device__ float g_h1[(size_t)MAXN * COUT];

typedef unsigned long long ull;

__device__ __forceinline__ ull pack2(float a, float b) {
    ull r; asm("mov.b64 %0, {%1, %2};" : "=l"(r) : "f"(a), "f"(b)); return r;
}
__device__ __forceinline__ float2 unpack2(ull v) {
    float2 f; asm("mov.b64 {%0, %1}, %2;" : "=f"(f.x), "=f"(f.y) : "l"(v)); return f;
}
__device__ __forceinline__ ull fma2(ull a, ull b, ull c) {
    ull d; asm("fma.rn.f32x2 %0, %1, %2, %3;" : "=l"(d) : "l"(a), "l"(b), "l"(c)); return d;
}

// Warp tile: 32 voxels x 32 couts. lane = (tx: couts 4tx..4tx+3, ty: voxels 8ty..8ty+7).
// acc[j][p] : f32x2 over voxel pair (8ty+2p, 8ty+2p+1), cout 4tx+j.

// =====================================================================
// conv1: h1 = relu( sum_k mask*x[idx] @ W1[k] + b1 )
// =====================================================================
__global__ __launch_bounds__(256, 3)
void conv1_kernel(const float* __restrict__ x,
                  const float* __restrict__ W1,
                  const float* __restrict__ b1,
                  const int* __restrict__ nbr_idx,
                  const unsigned int* __restrict__ nbr_mask,
                  int n) {
    extern __shared__ ull smem_u[];
    ull* Wd = smem_u;                       // K2*CIN*COUT = 4608 ull (dup pairs)
    ull* bd = Wd + K2 * CIN * COUT;         // COUT
    float* tiles = (float*)(bd + COUT);     // 8 warps * CIN*ST floats

    const int t = threadIdx.x;
    const int lane = t & 31, w = t >> 5;
    const int tx = lane & 7, ty = lane >> 3;
    float* xt = tiles + w * (CIN * ST);
    const int v0w = blockIdx.x * 256 + w * 32;

    // staging map: q = lane&3 (16B chunk), rr = lane>>2 (row group 0..7)
    const int q = lane & 3, rr = lane >> 2;
    float4 st[4];

    auto load_tap = [&](int k) {
#pragma unroll
        for (int i = 0; i < 4; i++) {
            int v = v0w + rr + 8 * i;
            float4 g = make_float4(0.f, 0.f, 0.f, 0.f);
            if (v < n) {
                size_t off = (size_t)k * n + v;
                if (nbr_mask[off])
                    g = __ldg((const float4*)(x + (size_t)nbr_idx[off] * CIN + 4 * q));
            }
            st[i] = g;
        }
    };
    auto sts_tap = [&]() {
#pragma unroll
        for (int i = 0; i < 4; i++) {
            int vl = rr + 8 * i;
            xt[(4 * q + 0) * ST + vl] = st[i].x;
            xt[(4 * q + 1) * ST + vl] = st[i].y;
            xt[(4 * q + 2) * ST + vl] = st[i].z;
            xt[(4 * q + 3) * ST + vl] = st[i].w;
        }
    };

    load_tap(0);   // tap-0 gathers in flight during weight staging

    for (int i = t; i < K2 * CIN * COUT; i += 256) { float wv = W1[i]; Wd[i] = pack2(wv, wv); }
    if (t < COUT) { float bv = b1[t]; bd[t] = pack2(bv, bv); }
    __syncthreads();

    ull acc[4][4];
#pragma unroll
    for (int j = 0; j < 4; j++) {
        ull bv = bd[4 * tx + j];
#pragma unroll
        for (int p = 0; p < 4; p++) acc[j][p] = bv;
    }

    sts_tap();
    __syncwarp();

    for (int k = 0; k < K2; k++) {
        if (k < K2 - 1) load_tap(k + 1);      // next tap's LDGs overlap compute
        const ull* wk = Wd + k * (CIN * COUT);
#pragma unroll
        for (int c = 0; c < CIN; c++) {
            ull wv[4];
#pragma unroll
            for (int j = 0; j < 4; j++) wv[j] = wk[c * COUT + 4 * tx + j];
#pragma unroll
            for (int p = 0; p < 4; p++) {
                ull hh = *(const ull*)(xt + c * ST + 8 * ty + 2 * p);  // voxel pair
#pragma unroll
                for (int j = 0; j < 4; j++) acc[j][p] = fma2(hh, wv[j], acc[j][p]);
            }
        }
        if (k < K2 - 1) { __syncwarp(); sts_tap(); __syncwarp(); }
    }

#pragma unroll
    for (int p = 0; p < 4; p++) {
        float2 a0 = unpack2(acc[0][p]), a1 = unpack2(acc[1][p]);
        float2 a2 = unpack2(acc[2][p]), a3 = unpack2(acc[3][p]);
        int v = v0w + 8 * ty + 2 * p;
        if (v < n)
            *(float4*)(g_h1 + (size_t)v * COUT + 4 * tx) =
                make_float4(fmaxf(a0.x, 0.f), fmaxf(a1.x, 0.f), fmaxf(a2.x, 0.f), fmaxf(a3.x, 0.f));
        if (v + 1 < n)
            *(float4*)(g_h1 + (size_t)(v + 1) * COUT + 4 * tx) =
                make_float4(fmaxf(a0.y, 0.f), fmaxf(a1.y, 0.f), fmaxf(a2.y, 0.f), fmaxf(a3.y, 0.f));
    }
}

// =====================================================================
// conv2 + residual: out = relu( sum_k mask*h1[idx] @ W2[k] + b2 + x @ Wp + bp )
// =====================================================================
__global__ __launch_bounds__(256, 2)
void conv2_kernel(const float* __restrict__ x,
                  const float* __restrict__ W2,
                  const float* __restrict__ b2,
                  const float* __restrict__ Wp,
                  const float* __restrict__ bp,
                  const int* __restrict__ nbr_idx,
                  const unsigned int* __restrict__ nbr_mask,
                  float* __restrict__ out,
                  int n) {
    extern __shared__ ull smem_u[];
    ull* Wd2 = smem_u;                          // K2*COUT*COUT = 9216 ull
    ull* Wpd = Wd2 + K2 * COUT * COUT;          // CIN*COUT = 512 ull
    ull* bd  = Wpd + CIN * COUT;                // COUT
    float* tiles = (float*)(bd + COUT);         // 8 * COUT*ST floats

    const int t = threadIdx.x;
    const int lane = t & 31, w = t >> 5;
    const int tx = lane & 7, ty = lane >> 3;
    float* xt = tiles + w * (COUT * ST);
    const int v0w = blockIdx.x * 256 + w * 32;

    const int q8 = lane & 7, r8 = lane >> 3;    // conv tap staging (8 chunks/row)
    const int q4 = lane & 3, r4 = lane >> 2;    // proj staging (4 chunks/row)
    float4 st[8];

    auto load_tap = [&](int k) {
#pragma unroll
        for (int i = 0; i < 8; i++) {
            int v = v0w + r8 + 4 * i;
            float4 g = make_float4(0.f, 0.f, 0.f, 0.f);
            if (v < n) {
                size_t off = (size_t)k * n + v;
                if (nbr_mask[off])
                    g = __ldg((const float4*)(g_h1 + (size_t)nbr_idx[off] * COUT + 4 * q8));
            }
            st[i] = g;
        }
    };
    auto sts_tap = [&]() {
#pragma unroll
        for (int i = 0; i < 8; i++) {
            int vl = r8 + 4 * i;
            xt[(4 * q8 + 0) * ST + vl] = st[i].x;
            xt[(4 * q8 + 1) * ST + vl] = st[i].y;
            xt[(4 * q8 + 2) * ST + vl] = st[i].z;
            xt[(4 * q8 + 3) * ST + vl] = st[i].w;
        }
    };
    auto load_proj = [&]() {
#pragma unroll
        for (int i = 0; i < 4; i++) {
            int v = v0w + r4 + 8 * i;
            float4 g = make_float4(0.f, 0.f, 0.f, 0.f);
            if (v < n) g = __ldg((const float4*)(x + (size_t)v * CIN + 4 * q4));
            st[i] = g;
        }
    };
    auto sts_proj = [&]() {
#pragma unroll
        for (int i = 0; i < 4; i++) {
            int vl = r4 + 8 * i;
            xt[(4 * q4 + 0) * ST + vl] = st[i].x;
            xt[(4 * q4 + 1) * ST + vl] = st[i].y;
            xt[(4 * q4 + 2) * ST + vl] = st[i].z;
            xt[(4 * q4 + 3) * ST + vl] = st[i].w;
        }
    };

    load_proj();   // own-x loads in flight during weight staging

    for (int i = t; i < K2 * COUT * COUT; i += 256) { float wv = W2[i]; Wd2[i] = pack2(wv, wv); }
    for (int i = t; i < CIN * COUT; i += 256)       { float wv = Wp[i]; Wpd[i] = pack2(wv, wv); }
    if (t < COUT) { float bv = b2[t] + bp[t]; bd[t] = pack2(bv, bv); }
    __syncthreads();

    ull acc[4][4];
#pragma unroll
    for (int j = 0; j < 4; j++) {
        ull bv = bd[4 * tx + j];
#pragma unroll
        for (int p = 0; p < 4; p++) acc[j][p] = bv;
    }

    sts_proj();
    __syncwarp();
    load_tap(0);   // tap-0 gathers overlap the projection compute

    // residual projection: 16 c-steps from channels 0..15 of the tile
#pragma unroll
    for (int c = 0; c < CIN; c++) {
        ull wv[4];
#pragma unroll
        for (int j = 0; j < 4; j++) wv[j] = Wpd[c * COUT + 4 * tx + j];
#pragma unroll
        for (int p = 0; p < 4; p++) {
            ull hh = *(const ull*)(xt + c * ST + 8 * ty + 2 * p);
#pragma unroll
            for (int j = 0; j < 4; j++) acc[j][p] = fma2(hh, wv[j], acc[j][p]);
        }
    }

    __syncwarp(); sts_tap(); __syncwarp();

    for (int k = 0; k < K2; k++) {
        if (k < K2 - 1) load_tap(k + 1);
        const ull* wk = Wd2 + k * (COUT * COUT);
#pragma unroll
        for (int c = 0; c < COUT; c++) {
            ull wv[4];
#pragma unroll
            for (int j = 0; j < 4; j++) wv[j] = wk[c * COUT + 4 * tx + j];
#pragma unroll
            for (int p = 0; p < 4; p++) {
                ull hh = *(const ull*)(xt + c * ST + 8 * ty + 2 * p);
#pragma unroll
                for (int j = 0; j < 4; j++) acc[j][p] = fma2(hh, wv[j], acc[j][p]);
            }
        }
        if (k < K2 - 1) { __syncwarp(); sts_tap(); __syncwarp(); }
    }

#pragma unroll
    for (int p = 0; p < 4; p++) {
        float2 a0 = unpack2(acc[0][p]), a1 = unpack2(acc[1][p]);
        float2 a2 = unpack2(acc[2][p]), a3 = unpack2(acc[3][p]);
        int v = v0w + 8 * ty + 2 * p;
        if (v < n)
            *(float4*)(out + (size_t)v * COUT + 4 * tx) =
                make_float4(fmaxf(a0.x, 0.f), fmaxf(a1.x, 0.f), fmaxf(a2.x, 0.f), fmaxf(a3.x, 0.f));
        if (v + 1 < n)
            *(float4*)(out + (size_t)(v + 1) * COUT + 4 * tx) =
                make_float4(fmaxf(a0.y, 0.f), fmaxf(a1.y, 0.f), fmaxf(a2.y, 0.f), fmaxf(a3.y, 0.f));
    }
}

// =====================================================================
// Launch.  Input order: x, W1, b1, W2, b2, Wp, bp, nbr_idx, nbr_mask
// =====================================================================
extern "C" void kernel_launch(void* const* d_in, const int* in_sizes, int n_in,
                              void* d_out, int out_size) {
    const float* x  = (const float*)d_in[0];
    const float* W1 = (const float*)d_in[1];
    const float* b1 = (const float*)d_in[2];
    const float* W2 = (const float*)d_in[3];
    const float* b2 = (const float*)d_in[4];
    const float* Wp = (const float*)d_in[5];
    const float* bp = (const float*)d_in[6];
    const int* nbr_idx = (const int*)d_in[7];
    const unsigned int* nbr_mask = (const unsigned int*)d_in[8];
    float* out = (float*)d_out;

    int n = in_sizes[0] / CIN;
    if (n > MAXN) n = MAXN;

    const int smem1 = (K2 * CIN * COUT + COUT) * 8 + 8 * CIN * ST * 4;            // ~54.5 KB
    const int smem2 = (K2 * COUT * COUT + CIN * COUT + COUT) * 8 + 8 * COUT * ST * 4;  // ~113 KB

    cudaFuncSetAttribute(conv1_kernel, cudaFuncAttributeMaxDynamicSharedMemorySize, smem1);
    cudaFuncSetAttribute(conv2_kernel, cudaFuncAttributeMaxDynamicSharedMemorySize, smem2);

    int blocks = (n + 255) / 256;
    conv1_kernel<<<blocks, 256, smem1>>>(x, W1, b1, nbr_idx, nbr_mask, n);
    conv2_kernel<<<blocks, 256, smem2>>>(x, W2, b2, Wp, bp, nbr_idx, nbr_mask, out, n);
}